// round 15
// baseline (speedup 1.0000x reference)
#include <cuda_runtime.h>

// ---------------- problem constants ----------------
#define BB   4
#define TT_  8192
#define CIN  128
#define COUT 256
#define NL   40
#define TILE 64            // timesteps per CTA
#define NTHREADS 512
#define HB   (CIN*TT_)     // per-batch h plane: 1048576 floats

typedef unsigned long long ull;

// ---------------- device scratch (no allocs allowed) ----------------
__device__ float g_h[2 * BB * HB];        // ping-pong hidden state  (33.5 MB)
__device__ float g_skip[BB * HB];         // skip_sum                (16.8 MB)
__device__ float g_wc[NL * 2 * CIN * COUT];  // conv w transposed [l][k][c][o]
__device__ float g_wp[NL * CIN * CIN];       // post w transposed [l][c][o]
__device__ float g_l1t[CIN * CIN];           // lin1 transposed   [c][j]
__device__ float g_l2t[CIN * CIN];           // lin2 transposed   [j][j2]

// ---------------- f32x2 helpers (sm_103a packed fp32) ----------------
__device__ __forceinline__ ull pack2(float lo, float hi) {
    ull r; asm("mov.b64 %0, {%1,%2};" : "=l"(r) : "f"(lo), "f"(hi)); return r;
}
__device__ __forceinline__ void unpack2(ull v, float& lo, float& hi) {
    asm("mov.b64 {%0,%1}, %2;" : "=f"(lo), "=f"(hi) : "l"(v));
}
__device__ __forceinline__ void ffma2(ull& d, ull a, ull b) {
    asm("fma.rn.f32x2 %0, %1, %2, %0;" : "+l"(d) : "l"(a), "l"(b));
}
__device__ __forceinline__ ull fadd2(ull a, ull b) {
    ull r; asm("add.rn.f32x2 %0, %1, %2;" : "=l"(r) : "l"(a), "l"(b)); return r;
}

// ---------------- one-time per-run weight transposes ----------------
__global__ void prep_kernel(const float* __restrict__ conv_w,
                            const float* __restrict__ post_w,
                            const float* __restrict__ lin1_w,
                            const float* __restrict__ lin2_w) {
    const int stride = gridDim.x * blockDim.x;
    const int start = blockIdx.x * blockDim.x + threadIdx.x;
    const int N1 = NL * 2 * CIN * COUT;   // 2621440
    const int N2 = NL * CIN * CIN;        // 655360
    for (int idx = start; idx < N1; idx += stride) {
        int o = idx & 255;
        int c = (idx >> 8) & 127;
        int k = (idx >> 15) & 1;
        int l = idx >> 16;
        g_wc[idx] = conv_w[((l * COUT + o) * CIN + c) * 2 + k];
    }
    for (int idx = start; idx < N2; idx += stride) {
        int o = idx & 127;
        int c = (idx >> 7) & 127;
        int l = idx >> 14;
        g_wp[idx] = post_w[(l * CIN + o) * CIN + c];
    }
    for (int idx = start; idx < CIN * CIN; idx += stride) {
        int o = idx & 127;
        int c = idx >> 7;
        g_l1t[idx] = lin1_w[o * CIN + c];
        g_l2t[idx] = lin2_w[o * CIN + c];
    }
}

// ---------------- pre-net (causal conv k=3, 1->128) + zero skip_sum ----------------
__global__ void pre_kernel(const float* __restrict__ x,
                           const float* __restrict__ pre_w,
                           const float* __restrict__ pre_b) {
    const int stride = gridDim.x * blockDim.x;
    const int N = BB * CIN * TT_;   // 2^22
    for (int idx = blockIdx.x * blockDim.x + threadIdx.x; idx < N; idx += stride) {
        int t = idx & (TT_ - 1);
        int c = (idx >> 13) & 127;
        int b = idx >> 20;
        const float* xb = x + b * TT_;
        float w0 = pre_w[c * 3 + 0], w1 = pre_w[c * 3 + 1], w2 = pre_w[c * 3 + 2];
        float v = pre_b[c] + w2 * xb[t];
        if (t >= 1) v += w1 * xb[t - 1];
        if (t >= 2) v += w0 * xb[t - 2];
        g_h[idx] = v;          // parity-0 buffer, layout [b][c][t]
        g_skip[idx] = 0.f;
    }
}

// ---------------- fused WaveNet block: conv(K=2,dilated)+GLU+skip+post+residual ----------------
__global__ __launch_bounds__(NTHREADS, 1)
void layer_kernel(int layer, int dil, int parity,
                  const float* __restrict__ conv_b_all,
                  const float* __restrict__ post_b_all) {
    extern __shared__ float sm[];
    float* sh_hcur = sm;           // [128][64]   32 KB
    float* sh_hsh  = sm + 8192;    // [128][64]   32 KB (reused as skip)
    float* sh_w    = sm + 16384;   // [64][256]   64 KB (w chunk -> y -> wp)

    const int tid  = threadIdx.x;
    const int tile = blockIdx.x;        // 0..511
    const int b    = tile >> 7;
    const int t0   = (tile & 127) * TILE;

    const float* h_in  = g_h + (size_t)parity * (BB * HB) + (size_t)b * HB;
    float*       h_out = g_h + (size_t)(parity ^ 1) * (BB * HB) + (size_t)b * HB;
    const float* wc = g_wc + (size_t)layer * (2 * CIN * COUT);
    const float* cb = conv_b_all + layer * COUT;
    const float* pb = post_b_all + layer * CIN;
    float* skp = g_skip + (size_t)b * HB;

    // ---- stage h (current) : vectorized ----
    #pragma unroll
    for (int it = 0; it < 4; ++it) {
        int v = tid + it * NTHREADS;        // 0..2047
        int c = v >> 4, tq = v & 15;
        *(float4*)(sh_hcur + c * TILE + tq * 4) =
            *(const float4*)(h_in + c * TT_ + t0 + tq * 4);
    }
    // ---- stage h (shifted by dilation) : scalar with causal predicate ----
    #pragma unroll
    for (int it = 0; it < 16; ++it) {
        int v = tid + it * NTHREADS;        // 0..8191
        int c = v >> 6, t = v & 63;
        int ts = t0 + t - dil;
        sh_hsh[c * TILE + t] = (ts >= 0) ? h_in[c * TT_ + ts] : 0.f;
    }

    const int og = tid >> 3;          // 0..63  -> 4 output channels
    const int tg = tid & 7;           // 0..7   -> 8 timesteps
    const int o_base = og * 4;
    const int t_base = tg * 8;

    // ---- conv GEMM: y[256][64] ----
    ull acc[4][4];
    {
        float4 cbv = *(const float4*)(cb + o_base);
        #pragma unroll
        for (int p = 0; p < 4; ++p) {
            acc[0][p] = pack2(cbv.x, cbv.x);
            acc[1][p] = pack2(cbv.y, cbv.y);
            acc[2][p] = pack2(cbv.z, cbv.z);
            acc[3][p] = pack2(cbv.w, cbv.w);
        }
    }
    for (int cc = 0; cc < 128; cc += 32) {
        __syncthreads();
        // stage weight chunk [2][32][256]
        #pragma unroll
        for (int it = 0; it < 8; ++it) {
            int v = tid + it * NTHREADS;    // 0..4095 float4s
            int o4 = v & 63, row = v >> 6;  // row: kk*32+cl
            int kk = row >> 5, cl = row & 31;
            *(float4*)(sh_w + row * 256 + o4 * 4) =
                *(const float4*)(wc + kk * (CIN * COUT) + (cc + cl) * COUT + o4 * 4);
        }
        __syncthreads();
        #pragma unroll 4
        for (int cl = 0; cl < 32; ++cl) {
            int c = cc + cl;
            float4 w0 = *(const float4*)(sh_w + cl * 256 + o_base);
            float4 w1 = *(const float4*)(sh_w + (32 + cl) * 256 + o_base);
            ull w0d0 = pack2(w0.x, w0.x), w0d1 = pack2(w0.y, w0.y);
            ull w0d2 = pack2(w0.z, w0.z), w0d3 = pack2(w0.w, w0.w);
            ull w1d0 = pack2(w1.x, w1.x), w1d1 = pack2(w1.y, w1.y);
            ull w1d2 = pack2(w1.z, w1.z), w1d3 = pack2(w1.w, w1.w);
            const ull* hs = (const ull*)(sh_hsh + c * TILE + t_base);
            const ull* hc = (const ull*)(sh_hcur + c * TILE + t_base);
            #pragma unroll
            for (int p = 0; p < 4; ++p) {
                ull xs = hs[p], xc = hc[p];
                ffma2(acc[0][p], w0d0, xs); ffma2(acc[0][p], w1d0, xc);
                ffma2(acc[1][p], w0d1, xs); ffma2(acc[1][p], w1d1, xc);
                ffma2(acc[2][p], w0d2, xs); ffma2(acc[2][p], w1d2, xc);
                ffma2(acc[3][p], w0d3, xs); ffma2(acc[3][p], w1d3, xc);
            }
        }
    }
    __syncthreads();
    // ---- park y in smem (reuse weight region) ----
    float* sh_y = sh_w;
    #pragma unroll
    for (int j = 0; j < 4; ++j)
        #pragma unroll
        for (int p = 0; p < 4; ++p)
            *(ull*)(sh_y + (o_base + j) * TILE + t_base + 2 * p) = acc[j][p];
    __syncthreads();
    // ---- GLU + skip_sum accumulate; skip -> sh_hsh ----
    #pragma unroll
    for (int it = 0; it < 16; ++it) {
        int v = tid + it * NTHREADS;
        int c = v >> 6, t = v & 63;
        float a = sh_y[c * TILE + t];
        float g = sh_y[(c + 128) * TILE + t];
        float s = a * (1.f / (1.f + __expf(-g)));
        sh_hsh[c * TILE + t] = s;
        int gi = c * TT_ + t0 + t;
        skp[gi] += s;
    }
    __syncthreads();
    // ---- stage post weights [128][128] ----
    #pragma unroll
    for (int it = 0; it < 8; ++it) {
        int v = tid + it * NTHREADS;   // 0..4095 float4s
        *(float4*)(sh_w + v * 4) = *(const float4*)(g_wp + (size_t)layer * (CIN * CIN) + v * 4);
    }
    __syncthreads();
    // ---- post GEMM + residual -> h_out ----
    {
        const int o2 = og * 2;
        ull pacc[2][4];
        float2 pbv = *(const float2*)(pb + o2);
        #pragma unroll
        for (int p = 0; p < 4; ++p) {
            pacc[0][p] = pack2(pbv.x, pbv.x);
            pacc[1][p] = pack2(pbv.y, pbv.y);
        }
        #pragma unroll 4
        for (int c = 0; c < 128; ++c) {
            float2 wv = *(const float2*)(sh_w + c * 128 + o2);
            ull wd0 = pack2(wv.x, wv.x), wd1 = pack2(wv.y, wv.y);
            const ull* sk = (const ull*)(sh_hsh + c * TILE + t_base);
            #pragma unroll
            for (int p = 0; p < 4; ++p) {
                ull xv = sk[p];
                ffma2(pacc[0][p], wd0, xv);
                ffma2(pacc[1][p], wd1, xv);
            }
        }
        #pragma unroll
        for (int j = 0; j < 2; ++j) {
            const ull* hr = (const ull*)(sh_hcur + (o2 + j) * TILE + t_base);
            #pragma unroll
            for (int p = 0; p < 4; ++p) {
                ull r = fadd2(pacc[j][p], hr[p]);
                *(ull*)(h_out + (o2 + j) * TT_ + t0 + t_base + 2 * p) = r;
            }
        }
    }
}

// ---------------- head: relu -> lin1 -> relu -> lin2, [B,C,T] -> [T,B,C] ----------------
__global__ __launch_bounds__(NTHREADS, 1)
void final_kernel(const float* __restrict__ lin1_b,
                  const float* __restrict__ lin2_b,
                  float* __restrict__ out) {
    extern __shared__ float sm[];
    float* sh_s  = sm;           // relu(skip_sum) [128][64]
    float* sh_z  = sm + 8192;    // z1             [128][64]
    float* sh_wt = sm + 16384;   // weights        [128][128]

    const int tid  = threadIdx.x;
    const int tile = blockIdx.x;
    const int b    = tile >> 7;
    const int t0   = (tile & 127) * TILE;
    const float* skp = g_skip + (size_t)b * HB;

    #pragma unroll
    for (int it = 0; it < 4; ++it) {
        int v = tid + it * NTHREADS;
        int c = v >> 4, tq = v & 15;
        float4 x = *(const float4*)(skp + c * TT_ + t0 + tq * 4);
        x.x = fmaxf(x.x, 0.f); x.y = fmaxf(x.y, 0.f);
        x.z = fmaxf(x.z, 0.f); x.w = fmaxf(x.w, 0.f);
        *(float4*)(sh_s + c * TILE + tq * 4) = x;
    }
    #pragma unroll
    for (int it = 0; it < 8; ++it) {
        int v = tid + it * NTHREADS;
        *(float4*)(sh_wt + v * 4) = *(const float4*)(g_l1t + v * 4);
    }
    __syncthreads();

    const int og = tid >> 3;
    const int tg = tid & 7;
    const int o2 = og * 2;
    const int t_base = tg * 8;

    // GEMM1: z1 = relu(lin1 @ relu(skip) + b1)
    ull acc[2][4];
    {
        float2 bv = *(const float2*)(lin1_b + o2);
        #pragma unroll
        for (int p = 0; p < 4; ++p) { acc[0][p] = pack2(bv.x, bv.x); acc[1][p] = pack2(bv.y, bv.y); }
    }
    #pragma unroll 4
    for (int c = 0; c < 128; ++c) {
        float2 wv = *(const float2*)(sh_wt + c * 128 + o2);
        ull wd0 = pack2(wv.x, wv.x), wd1 = pack2(wv.y, wv.y);
        const ull* xr = (const ull*)(sh_s + c * TILE + t_base);
        #pragma unroll
        for (int p = 0; p < 4; ++p) { ull xv = xr[p]; ffma2(acc[0][p], wd0, xv); ffma2(acc[1][p], wd1, xv); }
    }
    // relu + park z1
    #pragma unroll
    for (int j = 0; j < 2; ++j)
        #pragma unroll
        for (int p = 0; p < 4; ++p) {
            float lo, hi; unpack2(acc[j][p], lo, hi);
            sh_z[(o2 + j) * TILE + t_base + 2 * p]     = fmaxf(lo, 0.f);
            sh_z[(o2 + j) * TILE + t_base + 2 * p + 1] = fmaxf(hi, 0.f);
        }
    __syncthreads();
    #pragma unroll
    for (int it = 0; it < 8; ++it) {
        int v = tid + it * NTHREADS;
        *(float4*)(sh_wt + v * 4) = *(const float4*)(g_l2t + v * 4);
    }
    __syncthreads();

    // GEMM2: out = lin2 @ z1 + b2, layout [T,B,128]
    ull acc2[2][4];
    {
        float2 bv = *(const float2*)(lin2_b + o2);
        #pragma unroll
        for (int p = 0; p < 4; ++p) { acc2[0][p] = pack2(bv.x, bv.x); acc2[1][p] = pack2(bv.y, bv.y); }
    }
    #pragma unroll 4
    for (int c = 0; c < 128; ++c) {
        float2 wv = *(const float2*)(sh_wt + c * 128 + o2);
        ull wd0 = pack2(wv.x, wv.x), wd1 = pack2(wv.y, wv.y);
        const ull* xr = (const ull*)(sh_z + c * TILE + t_base);
        #pragma unroll
        for (int p = 0; p < 4; ++p) { ull xv = xr[p]; ffma2(acc2[0][p], wd0, xv); ffma2(acc2[1][p], wd1, xv); }
    }
    #pragma unroll
    for (int j = 0; j < 2; ++j)
        #pragma unroll
        for (int p = 0; p < 4; ++p) {
            float lo, hi; unpack2(acc2[j][p], lo, hi);
            int t = t0 + t_base + 2 * p;
            out[((size_t)t * BB + b) * CIN + o2 + j]       = lo;
            out[((size_t)(t + 1) * BB + b) * CIN + o2 + j] = hi;
        }
}

// ---------------- host launcher ----------------
extern "C" void kernel_launch(void* const* d_in, const int* in_sizes, int n_in,
                              void* d_out, int out_size) {
    const float* x      = (const float*)d_in[0];
    const float* pre_w  = (const float*)d_in[1];
    const float* pre_b  = (const float*)d_in[2];
    const float* conv_w = (const float*)d_in[3];
    const float* conv_b = (const float*)d_in[4];
    const float* post_w = (const float*)d_in[5];
    const float* post_b = (const float*)d_in[6];
    const float* lin1_w = (const float*)d_in[7];
    const float* lin1_b = (const float*)d_in[8];
    const float* lin2_w = (const float*)d_in[9];
    const float* lin2_b = (const float*)d_in[10];
    float* out = (float*)d_out;

    const int SMEM = 32768 * (int)sizeof(float);   // 128 KB
    cudaFuncSetAttribute(layer_kernel, cudaFuncAttributeMaxDynamicSharedMemorySize, SMEM);
    cudaFuncSetAttribute(final_kernel, cudaFuncAttributeMaxDynamicSharedMemorySize, SMEM);

    prep_kernel<<<2048, 256>>>(conv_w, post_w, lin1_w, lin2_w);
    pre_kernel<<<2048, 256>>>(x, pre_w, pre_b);

    int parity = 0;
    for (int i = 0; i < NL; ++i) {
        int d = 1 << (i % 10);
        layer_kernel<<<BB * (TT_ / TILE), NTHREADS, SMEM>>>(i, d, parity, conv_b, post_b);
        parity ^= 1;
    }
    final_kernel<<<BB * (TT_ / TILE), NTHREADS, SMEM>>>(lin1_b, lin2_b, out);
}

// round 16
// speedup vs baseline: 1.0554x; 1.0554x over previous
#include <cuda_runtime.h>

// ---------------- problem constants ----------------
#define BB   4
#define TT_  8192
#define CIN  128
#define COUT 256
#define NL   40
#define TILE 64            // timesteps per CTA
#define NTHREADS 512
#define HB   (CIN*TT_)     // per-batch h plane: 1048576 floats

typedef unsigned long long ull;

// ---------------- device scratch (no allocs allowed) ----------------
__device__ float g_h[2 * BB * HB];        // ping-pong hidden state  (33.5 MB)
__device__ float g_skip[BB * HB];         // skip_sum                (16.8 MB)
__device__ float g_wc[NL * 2 * CIN * COUT];  // conv w transposed [l][k][c][o]
__device__ float g_wp[NL * CIN * CIN];       // post w transposed [l][c][o]
__device__ float g_l1t[CIN * CIN];           // lin1 transposed   [c][j]
__device__ float g_l2t[CIN * CIN];           // lin2 transposed   [j][j2]

// ---------------- f32x2 helpers (sm_103a packed fp32) ----------------
__device__ __forceinline__ ull pack2(float lo, float hi) {
    ull r; asm("mov.b64 %0, {%1,%2};" : "=l"(r) : "f"(lo), "f"(hi)); return r;
}
__device__ __forceinline__ void unpack2(ull v, float& lo, float& hi) {
    asm("mov.b64 {%0,%1}, %2;" : "=f"(lo), "=f"(hi) : "l"(v));
}
__device__ __forceinline__ void ffma2(ull& d, ull a, ull b) {
    asm("fma.rn.f32x2 %0, %1, %2, %0;" : "+l"(d) : "l"(a), "l"(b));
}
__device__ __forceinline__ ull fadd2(ull a, ull b) {
    ull r; asm("add.rn.f32x2 %0, %1, %2;" : "=l"(r) : "l"(a), "l"(b)); return r;
}

// ---------------- one-time per-run weight transposes ----------------
__global__ void prep_kernel(const float* __restrict__ conv_w,
                            const float* __restrict__ post_w,
                            const float* __restrict__ lin1_w,
                            const float* __restrict__ lin2_w) {
    const int stride = gridDim.x * blockDim.x;
    const int start = blockIdx.x * blockDim.x + threadIdx.x;
    const int N1 = NL * 2 * CIN * COUT;   // 2621440
    const int N2 = NL * CIN * CIN;        // 655360
    for (int idx = start; idx < N1; idx += stride) {
        int o = idx & 255;
        int c = (idx >> 8) & 127;
        int k = (idx >> 15) & 1;
        int l = idx >> 16;
        g_wc[idx] = conv_w[((l * COUT + o) * CIN + c) * 2 + k];
    }
    for (int idx = start; idx < N2; idx += stride) {
        int o = idx & 127;
        int c = (idx >> 7) & 127;
        int l = idx >> 14;
        g_wp[idx] = post_w[(l * CIN + o) * CIN + c];
    }
    for (int idx = start; idx < CIN * CIN; idx += stride) {
        int o = idx & 127;
        int c = idx >> 7;
        g_l1t[idx] = lin1_w[o * CIN + c];
        g_l2t[idx] = lin2_w[o * CIN + c];
    }
}

// ---------------- pre-net (causal conv k=3, 1->128) + zero skip_sum ----------------
__global__ void pre_kernel(const float* __restrict__ x,
                           const float* __restrict__ pre_w,
                           const float* __restrict__ pre_b) {
    const int stride = gridDim.x * blockDim.x;
    const int N = BB * CIN * TT_;   // 2^22
    for (int idx = blockIdx.x * blockDim.x + threadIdx.x; idx < N; idx += stride) {
        int t = idx & (TT_ - 1);
        int c = (idx >> 13) & 127;
        int b = idx >> 20;
        const float* xb = x + b * TT_;
        float w0 = pre_w[c * 3 + 0], w1 = pre_w[c * 3 + 1], w2 = pre_w[c * 3 + 2];
        float v = pre_b[c] + w2 * xb[t];
        if (t >= 1) v += w1 * xb[t - 1];
        if (t >= 2) v += w0 * xb[t - 2];
        g_h[idx] = v;          // parity-0 buffer, layout [b][c][t]
        g_skip[idx] = 0.f;
    }
}

// ---------------- fused WaveNet block: conv(K=2,dilated)+GLU+skip+post+residual ----------------
__global__ __launch_bounds__(NTHREADS, 1)
void layer_kernel(int layer, int dil, int parity,
                  const float* __restrict__ conv_b_all,
                  const float* __restrict__ post_b_all) {
    extern __shared__ float sm[];
    float* sh_hcur = sm;           // [128][64]   32 KB
    float* sh_hsh  = sm + 8192;    // [128][64]   32 KB (reused as skip)
    float* sh_w    = sm + 16384;   // [64][256]   64 KB (w chunk -> y -> wp)

    const int tid  = threadIdx.x;
    const int tile = blockIdx.x;        // 0..511
    const int b    = tile >> 7;
    const int t0   = (tile & 127) * TILE;

    const float* h_in  = g_h + (size_t)parity * (BB * HB) + (size_t)b * HB;
    float*       h_out = g_h + (size_t)(parity ^ 1) * (BB * HB) + (size_t)b * HB;
    const float* wc = g_wc + (size_t)layer * (2 * CIN * COUT);
    const float* cb = conv_b_all + layer * COUT;
    const float* pb = post_b_all + layer * CIN;
    float* skp = g_skip + (size_t)b * HB;

    // ---- stage h (current) : vectorized ----
    #pragma unroll
    for (int it = 0; it < 4; ++it) {
        int v = tid + it * NTHREADS;        // 0..2047
        int c = v >> 4, tq = v & 15;
        *(float4*)(sh_hcur + c * TILE + tq * 4) =
            *(const float4*)(h_in + c * TT_ + t0 + tq * 4);
    }
    // ---- stage h (shifted by dilation) : scalar with causal predicate ----
    #pragma unroll
    for (int it = 0; it < 16; ++it) {
        int v = tid + it * NTHREADS;        // 0..8191
        int c = v >> 6, t = v & 63;
        int ts = t0 + t - dil;
        sh_hsh[c * TILE + t] = (ts >= 0) ? h_in[c * TT_ + ts] : 0.f;
    }

    const int og = tid >> 3;          // 0..63  -> 4 output channels
    const int tg = tid & 7;           // 0..7   -> 8 timesteps
    const int o_base = og * 4;
    const int t_base = tg * 8;

    // ---- conv GEMM: y[256][64] ----
    ull acc[4][4];
    {
        float4 cbv = *(const float4*)(cb + o_base);
        #pragma unroll
        for (int p = 0; p < 4; ++p) {
            acc[0][p] = pack2(cbv.x, cbv.x);
            acc[1][p] = pack2(cbv.y, cbv.y);
            acc[2][p] = pack2(cbv.z, cbv.z);
            acc[3][p] = pack2(cbv.w, cbv.w);
        }
    }
    for (int cc = 0; cc < 128; cc += 32) {
        __syncthreads();
        // stage weight chunk [2][32][256]
        #pragma unroll
        for (int it = 0; it < 8; ++it) {
            int v = tid + it * NTHREADS;    // 0..4095 float4s
            int o4 = v & 63, row = v >> 6;  // row: kk*32+cl
            int kk = row >> 5, cl = row & 31;
            *(float4*)(sh_w + row * 256 + o4 * 4) =
                *(const float4*)(wc + kk * (CIN * COUT) + (cc + cl) * COUT + o4 * 4);
        }
        __syncthreads();
        #pragma unroll 4
        for (int cl = 0; cl < 32; ++cl) {
            int c = cc + cl;
            float4 w0 = *(const float4*)(sh_w + cl * 256 + o_base);
            float4 w1 = *(const float4*)(sh_w + (32 + cl) * 256 + o_base);
            ull w0d0 = pack2(w0.x, w0.x), w0d1 = pack2(w0.y, w0.y);
            ull w0d2 = pack2(w0.z, w0.z), w0d3 = pack2(w0.w, w0.w);
            ull w1d0 = pack2(w1.x, w1.x), w1d1 = pack2(w1.y, w1.y);
            ull w1d2 = pack2(w1.z, w1.z), w1d3 = pack2(w1.w, w1.w);
            const ull* hs = (const ull*)(sh_hsh + c * TILE + t_base);
            const ull* hc = (const ull*)(sh_hcur + c * TILE + t_base);
            #pragma unroll
            for (int p = 0; p < 4; ++p) {
                ull xs = hs[p], xc = hc[p];
                ffma2(acc[0][p], w0d0, xs); ffma2(acc[0][p], w1d0, xc);
                ffma2(acc[1][p], w0d1, xs); ffma2(acc[1][p], w1d1, xc);
                ffma2(acc[2][p], w0d2, xs); ffma2(acc[2][p], w1d2, xc);
                ffma2(acc[3][p], w0d3, xs); ffma2(acc[3][p], w1d3, xc);
            }
        }
    }
    __syncthreads();
    // ---- park y in smem (reuse weight region) ----
    float* sh_y = sh_w;
    #pragma unroll
    for (int j = 0; j < 4; ++j)
        #pragma unroll
        for (int p = 0; p < 4; ++p)
            *(ull*)(sh_y + (o_base + j) * TILE + t_base + 2 * p) = acc[j][p];
    __syncthreads();
    // ---- GLU + skip_sum accumulate; skip -> sh_hsh ----
    #pragma unroll
    for (int it = 0; it < 16; ++it) {
        int v = tid + it * NTHREADS;
        int c = v >> 6, t = v & 63;
        float a = sh_y[c * TILE + t];
        float g = sh_y[(c + 128) * TILE + t];
        float s = a * (1.f / (1.f + __expf(-g)));
        sh_hsh[c * TILE + t] = s;
        int gi = c * TT_ + t0 + t;
        skp[gi] += s;
    }
    __syncthreads();
    // ---- stage post weights [128][128] ----
    #pragma unroll
    for (int it = 0; it < 8; ++it) {
        int v = tid + it * NTHREADS;   // 0..4095 float4s
        *(float4*)(sh_w + v * 4) = *(const float4*)(g_wp + (size_t)layer * (CIN * CIN) + v * 4);
    }
    __syncthreads();
    // ---- post GEMM + residual -> h_out ----
    {
        const int o2 = og * 2;
        ull pacc[2][4];
        float2 pbv = *(const float2*)(pb + o2);
        #pragma unroll
        for (int p = 0; p < 4; ++p) {
            pacc[0][p] = pack2(pbv.x, pbv.x);
            pacc[1][p] = pack2(pbv.y, pbv.y);
        }
        #pragma unroll 4
        for (int c = 0; c < 128; ++c) {
            float2 wv = *(const float2*)(sh_w + c * 128 + o2);
            ull wd0 = pack2(wv.x, wv.x), wd1 = pack2(wv.y, wv.y);
            const ull* sk = (const ull*)(sh_hsh + c * TILE + t_base);
            #pragma unroll
            for (int p = 0; p < 4; ++p) {
                ull xv = sk[p];
                ffma2(pacc[0][p], wd0, xv);
                ffma2(pacc[1][p], wd1, xv);
            }
        }
        #pragma unroll
        for (int j = 0; j < 2; ++j) {
            const ull* hr = (const ull*)(sh_hcur + (o2 + j) * TILE + t_base);
            #pragma unroll
            for (int p = 0; p < 4; ++p) {
                ull r = fadd2(pacc[j][p], hr[p]);
                *(ull*)(h_out + (o2 + j) * TT_ + t0 + t_base + 2 * p) = r;
            }
        }
    }
}

// ---------------- head: relu -> lin1 -> relu -> lin2, [B,C,T] -> [T,B,C] ----------------
__global__ __launch_bounds__(NTHREADS, 1)
void final_kernel(const float* __restrict__ lin1_b,
                  const float* __restrict__ lin2_b,
                  float* __restrict__ out) {
    extern __shared__ float sm[];
    float* sh_s  = sm;           // relu(skip_sum) [128][64]
    float* sh_z  = sm + 8192;    // z1             [128][64]
    float* sh_wt = sm + 16384;   // weights        [128][128]

    const int tid  = threadIdx.x;
    const int tile = blockIdx.x;
    const int b    = tile >> 7;
    const int t0   = (tile & 127) * TILE;
    const float* skp = g_skip + (size_t)b * HB;

    #pragma unroll
    for (int it = 0; it < 4; ++it) {
        int v = tid + it * NTHREADS;
        int c = v >> 4, tq = v & 15;
        float4 x = *(const float4*)(skp + c * TT_ + t0 + tq * 4);
        x.x = fmaxf(x.x, 0.f); x.y = fmaxf(x.y, 0.f);
        x.z = fmaxf(x.z, 0.f); x.w = fmaxf(x.w, 0.f);
        *(float4*)(sh_s + c * TILE + tq * 4) = x;
    }
    #pragma unroll
    for (int it = 0; it < 8; ++it) {
        int v = tid + it * NTHREADS;
        *(float4*)(sh_wt + v * 4) = *(const float4*)(g_l1t + v * 4);
    }
    __syncthreads();

    const int og = tid >> 3;
    const int tg = tid & 7;
    const int o2 = og * 2;
    const int t_base = tg * 8;

    // GEMM1: z1 = relu(lin1 @ relu(skip) + b1)
    ull acc[2][4];
    {
        float2 bv = *(const float2*)(lin1_b + o2);
        #pragma unroll
        for (int p = 0; p < 4; ++p) { acc[0][p] = pack2(bv.x, bv.x); acc[1][p] = pack2(bv.y, bv.y); }
    }
    #pragma unroll 4
    for (int c = 0; c < 128; ++c) {
        float2 wv = *(const float2*)(sh_wt + c * 128 + o2);
        ull wd0 = pack2(wv.x, wv.x), wd1 = pack2(wv.y, wv.y);
        const ull* xr = (const ull*)(sh_s + c * TILE + t_base);
        #pragma unroll
        for (int p = 0; p < 4; ++p) { ull xv = xr[p]; ffma2(acc[0][p], wd0, xv); ffma2(acc[1][p], wd1, xv); }
    }
    // relu + park z1
    #pragma unroll
    for (int j = 0; j < 2; ++j)
        #pragma unroll
        for (int p = 0; p < 4; ++p) {
            float lo, hi; unpack2(acc[j][p], lo, hi);
            sh_z[(o2 + j) * TILE + t_base + 2 * p]     = fmaxf(lo, 0.f);
            sh_z[(o2 + j) * TILE + t_base + 2 * p + 1] = fmaxf(hi, 0.f);
        }
    __syncthreads();
    #pragma unroll
    for (int it = 0; it < 8; ++it) {
        int v = tid + it * NTHREADS;
        *(float4*)(sh_wt + v * 4) = *(const float4*)(g_l2t + v * 4);
    }
    __syncthreads();

    // GEMM2: out = lin2 @ z1 + b2, layout [T,B,128]
    ull acc2[2][4];
    {
        float2 bv = *(const float2*)(lin2_b + o2);
        #pragma unroll
        for (int p = 0; p < 4; ++p) { acc2[0][p] = pack2(bv.x, bv.x); acc2[1][p] = pack2(bv.y, bv.y); }
    }
    #pragma unroll 4
    for (int c = 0; c < 128; ++c) {
        float2 wv = *(const float2*)(sh_wt + c * 128 + o2);
        ull wd0 = pack2(wv.x, wv.x), wd1 = pack2(wv.y, wv.y);
        const ull* xr = (const ull*)(sh_z + c * TILE + t_base);
        #pragma unroll
        for (int p = 0; p < 4; ++p) { ull xv = xr[p]; ffma2(acc2[0][p], wd0, xv); ffma2(acc2[1][p], wd1, xv); }
    }
    #pragma unroll
    for (int j = 0; j < 2; ++j)
        #pragma unroll
        for (int p = 0; p < 4; ++p) {
            float lo, hi; unpack2(acc2[j][p], lo, hi);
            int t = t0 + t_base + 2 * p;
            out[((size_t)t * BB + b) * CIN + o2 + j]       = lo;
            out[((size_t)(t + 1) * BB + b) * CIN + o2 + j] = hi;
        }
}

// ---------------- host launcher ----------------
extern "C" void kernel_launch(void* const* d_in, const int* in_sizes, int n_in,
                              void* d_out, int out_size) {
    const float* x      = (const float*)d_in[0];
    const float* pre_w  = (const float*)d_in[1];
    const float* pre_b  = (const float*)d_in[2];
    const float* conv_w = (const float*)d_in[3];
    const float* conv_b = (const float*)d_in[4];
    const float* post_w = (const float*)d_in[5];
    const float* post_b = (const float*)d_in[6];
    const float* lin1_w = (const float*)d_in[7];
    const float* lin1_b = (const float*)d_in[8];
    const float* lin2_w = (const float*)d_in[9];
    const float* lin2_b = (const float*)d_in[10];
    float* out = (float*)d_out;

    const int SMEM = 32768 * (int)sizeof(float);   // 128 KB
    cudaFuncSetAttribute(layer_kernel, cudaFuncAttributeMaxDynamicSharedMemorySize, SMEM);
    cudaFuncSetAttribute(final_kernel, cudaFuncAttributeMaxDynamicSharedMemorySize, SMEM);

    prep_kernel<<<2048, 256>>>(conv_w, post_w, lin1_w, lin2_w);
    pre_kernel<<<2048, 256>>>(x, pre_w, pre_b);

    int parity = 0;
    for (int i = 0; i < NL; ++i) {
        int d = 1 << (i % 10);
        layer_kernel<<<BB * (TT_ / TILE), NTHREADS, SMEM>>>(i, d, parity, conv_b, post_b);
        parity ^= 1;
    }
    final_kernel<<<BB * (TT_ / TILE), NTHREADS, SMEM>>>(lin1_b, lin2_b, out);
}

// round 17
// speedup vs baseline: 1.1761x; 1.1144x over previous
#include <cuda_runtime.h>

// ---------------- problem constants ----------------
#define BB   4
#define TT_  8192
#define CIN  128
#define NL   40
#define TILE 64            // timesteps per CTA
#define NTH  256
#define HB   (CIN*TT_)     // per-batch h plane

typedef unsigned long long ull;

// ---------------- device scratch (no allocs allowed) ----------------
__device__ float g_h[2 * BB * HB];          // ping-pong hidden state
__device__ float g_skip[BB * HB];           // skip_sum
__device__ float g_wc[NL * 128 * 64 * 8];   // conv w:  [l][c][og][k*4+j]
__device__ float g_wp[NL * 64 * 64 * 4];    // post w:  [l][c2][og][4]
__device__ float g_l1t[64 * 64 * 4];        // lin1:    [c2][og][4]
__device__ float g_l2t[64 * 64 * 4];        // lin2:    [c2][og][4]

// ---------------- f32x2 helpers (sm_103a packed fp32) ----------------
__device__ __forceinline__ ull pack2(float lo, float hi) {
    ull r; asm("mov.b64 %0, {%1,%2};" : "=l"(r) : "f"(lo), "f"(hi)); return r;
}
__device__ __forceinline__ void unpack2(ull v, float& lo, float& hi) {
    asm("mov.b64 {%0,%1}, %2;" : "=f"(lo), "=f"(hi) : "l"(v));
}
__device__ __forceinline__ void ffma2(ull& d, ull a, ull b) {
    asm("fma.rn.f32x2 %0, %1, %2, %0;" : "+l"(d) : "l"(a), "l"(b));
}
__device__ __forceinline__ ull fadd2(ull a, ull b) {
    ull r; asm("add.rn.f32x2 %0, %1, %2;" : "=l"(r) : "l"(a), "l"(b)); return r;
}

// ---------------- one-time weight permutations ----------------
// conv: per (l,c,og) 8 floats: q = k*4+j, j in {a0,a1,g0,g1}
//   o(j) = j<2 ? 2*og+j : 128 + 2*og + (j-2)
// post/lin: per (l,c2,og) 4 floats: r -> (c = 2*c2+(r>>1), o = 2*og+(r&1))
__global__ void prep_kernel(const float* __restrict__ conv_w,
                            const float* __restrict__ post_w,
                            const float* __restrict__ lin1_w,
                            const float* __restrict__ lin2_w) {
    const int stride = gridDim.x * blockDim.x;
    const int start = blockIdx.x * blockDim.x + threadIdx.x;
    const int N1 = NL << 16;          // 40*65536
    const int N2 = NL << 14;          // 40*16384
    for (int idx = start; idx < N1; idx += stride) {
        int q  = idx & 7;
        int og = (idx >> 3) & 63;
        int c  = (idx >> 9) & 127;
        int l  = idx >> 16;
        int k  = q >> 2, j = q & 3;
        int o  = (j < 2) ? (2 * og + j) : (128 + 2 * og + (j - 2));
        g_wc[idx] = conv_w[((l * 256 + o) * 128 + c) * 2 + k];
    }
    for (int idx = start; idx < N2; idx += stride) {
        int r  = idx & 3;
        int og = (idx >> 2) & 63;
        int c2 = (idx >> 8) & 63;
        int l  = idx >> 14;
        int c  = 2 * c2 + (r >> 1);
        int o  = 2 * og + (r & 1);
        g_wp[idx] = post_w[(l * 128 + o) * 128 + c];
    }
    for (int idx = start; idx < 16384; idx += stride) {
        int r  = idx & 3;
        int og = (idx >> 2) & 63;
        int c2 = idx >> 8;
        int c  = 2 * c2 + (r >> 1);
        int o  = 2 * og + (r & 1);
        g_l1t[idx] = lin1_w[o * 128 + c];
        g_l2t[idx] = lin2_w[o * 128 + c];
    }
}

// ---------------- pre-net (causal conv k=3, 1->128) + zero skip_sum ----------------
__global__ void pre_kernel(const float* __restrict__ x,
                           const float* __restrict__ pre_w,
                           const float* __restrict__ pre_b) {
    const int stride = gridDim.x * blockDim.x;
    const int N = BB * CIN * TT_;
    for (int idx = blockIdx.x * blockDim.x + threadIdx.x; idx < N; idx += stride) {
        int t = idx & (TT_ - 1);
        int c = (idx >> 13) & 127;
        int b = idx >> 20;
        const float* xb = x + b * TT_;
        float w0 = pre_w[c * 3 + 0], w1 = pre_w[c * 3 + 1], w2 = pre_w[c * 3 + 2];
        float v = pre_b[c] + w2 * xb[t];
        if (t >= 1) v += w1 * xb[t - 1];
        if (t >= 2) v += w0 * xb[t - 2];
        g_h[idx] = v;
        g_skip[idx] = 0.f;
    }
}

// ---------------- fused WaveNet block ----------------
// 256 threads, 96KB smem, 2 CTAs/SM. Each thread: out-channels
// {2og, 2og+1} (a) + {128+2og, 128+2og+1} (g), 16 timesteps (tg*16..+15).
// GLU happens in registers; only 2 __syncthreads per layer.
__global__ __launch_bounds__(NTH, 2)
void layer_kernel(int layer, int dil, int parity,
                  const float* __restrict__ cb_all,
                  const float* __restrict__ pb_all) {
    extern __shared__ float sm[];
    float* sh_hcur = sm;            // [128][64] 32KB
    float* sh_hsh  = sm + 8192;     // [128][64] 32KB
    float* sh_s    = sm + 16384;    // [128][64] 32KB

    const int tid  = threadIdx.x;
    const int tile = blockIdx.x;        // 0..511
    const int b    = tile >> 7;
    const int t0   = (tile & 127) * TILE;

    const float* h_in  = g_h + (size_t)parity * (BB * HB) + (size_t)b * HB;
    float*       h_out = g_h + (size_t)(parity ^ 1) * (BB * HB) + (size_t)b * HB;
    float*       skp   = g_skip + (size_t)b * HB;

    // ---- stage h (current), vectorized ----
    #pragma unroll
    for (int it = 0; it < 8; ++it) {
        int v = tid + it * NTH;         // 0..2047 float4s
        int c = v >> 4, q = v & 15;
        *(float4*)(sh_hcur + c * TILE + q * 4) =
            __ldg((const float4*)(h_in + c * TT_ + t0 + q * 4));
    }
    // ---- stage h shifted by dilation (scalar, coalesced, causal pred) ----
    #pragma unroll
    for (int it = 0; it < 32; ++it) {
        int v = tid + it * NTH;         // 0..8191
        int c = v >> 6, t = v & 63;
        int ts = t0 + t - dil;
        sh_hsh[c * TILE + t] = (ts >= 0) ? __ldg(h_in + c * TT_ + ts) : 0.f;
    }
    __syncthreads();

    const int og = tid >> 2;            // 0..63
    const int tg = tid & 3;             // 0..3
    const int tb = tg * 16;
    const int ca = 2 * og;              // a channels: ca, ca+1; g: ca+128, ca+129

    // ---- conv GEMM: accumulate a & g halves in registers ----
    ull aA0[8], aA1[8], aG0[8], aG1[8];
    {
        const float* cb = cb_all + layer * 256;
        float b0 = cb[ca], b1 = cb[ca + 1], b2 = cb[ca + 128], b3 = cb[ca + 129];
        #pragma unroll
        for (int p = 0; p < 8; ++p) {
            aA0[p] = pack2(b0, b0); aA1[p] = pack2(b1, b1);
            aG0[p] = pack2(b2, b2); aG1[p] = pack2(b3, b3);
        }
    }
    const float4* wcp = (const float4*)(g_wc + ((size_t)layer << 16)) + og * 2;
    #pragma unroll 1
    for (int c = 0; c < 128; ++c) {
        float4 w0 = __ldg(wcp + c * 128);       // tap k=0 (shifted): a0,a1,g0,g1
        float4 w1 = __ldg(wcp + c * 128 + 1);   // tap k=1 (current)
        ull wA0s = pack2(w0.x, w0.x), wA1s = pack2(w0.y, w0.y);
        ull wG0s = pack2(w0.z, w0.z), wG1s = pack2(w0.w, w0.w);
        ull wA0c = pack2(w1.x, w1.x), wA1c = pack2(w1.y, w1.y);
        ull wG0c = pack2(w1.z, w1.z), wG1c = pack2(w1.w, w1.w);
        const ull* hs = (const ull*)(sh_hsh  + c * TILE + tb);
        const ull* hc = (const ull*)(sh_hcur + c * TILE + tb);
        #pragma unroll
        for (int p = 0; p < 8; ++p) {
            ull xs = hs[p], xc = hc[p];
            ffma2(aA0[p], wA0s, xs); ffma2(aA0[p], wA0c, xc);
            ffma2(aA1[p], wA1s, xs); ffma2(aA1[p], wA1c, xc);
            ffma2(aG0[p], wG0s, xs); ffma2(aG0[p], wG0c, xc);
            ffma2(aG1[p], wG1s, xs); ffma2(aG1[p], wG1c, xc);
        }
    }

    // ---- GLU in registers ----
    float s0[16], s1[16];
    #pragma unroll
    for (int p = 0; p < 8; ++p) {
        float al, ah, gl, gh;
        unpack2(aA0[p], al, ah); unpack2(aG0[p], gl, gh);
        s0[2 * p]     = al * (1.f / (1.f + __expf(-gl)));
        s0[2 * p + 1] = ah * (1.f / (1.f + __expf(-gh)));
        unpack2(aA1[p], al, ah); unpack2(aG1[p], gl, gh);
        s1[2 * p]     = al * (1.f / (1.f + __expf(-gl)));
        s1[2 * p + 1] = ah * (1.f / (1.f + __expf(-gh)));
    }
    // park s in its own smem region (no prior sync needed) + skip_sum RMW
    #pragma unroll
    for (int q = 0; q < 4; ++q) {
        *(float4*)(sh_s + ca * TILE + tb + 4 * q) =
            make_float4(s0[4 * q], s0[4 * q + 1], s0[4 * q + 2], s0[4 * q + 3]);
        *(float4*)(sh_s + (ca + 1) * TILE + tb + 4 * q) =
            make_float4(s1[4 * q], s1[4 * q + 1], s1[4 * q + 2], s1[4 * q + 3]);
    }
    #pragma unroll
    for (int q = 0; q < 4; ++q) {
        float4* p0 = (float4*)(skp + ca * TT_ + t0 + tb + 4 * q);
        float4 v0 = *p0;
        v0.x += s0[4*q]; v0.y += s0[4*q+1]; v0.z += s0[4*q+2]; v0.w += s0[4*q+3];
        *p0 = v0;
        float4* p1 = (float4*)(skp + (ca + 1) * TT_ + t0 + tb + 4 * q);
        float4 v1 = *p1;
        v1.x += s1[4*q]; v1.y += s1[4*q+1]; v1.z += s1[4*q+2]; v1.w += s1[4*q+3];
        *p1 = v1;
    }
    __syncthreads();

    // ---- post GEMM (128x128) + residual ----
    ull o0[8], o1[8];
    {
        const float* pb = pb_all + layer * 128;
        float pb0 = pb[ca], pb1 = pb[ca + 1];
        #pragma unroll
        for (int p = 0; p < 8; ++p) { o0[p] = pack2(pb0, pb0); o1[p] = pack2(pb1, pb1); }
    }
    const float4* wpp = (const float4*)(g_wp + (size_t)layer * 16384) + og;
    #pragma unroll 2
    for (int c2 = 0; c2 < 64; ++c2) {
        float4 w = __ldg(wpp + c2 * 64);    // {c,o0},{c,o1},{c+1,o0},{c+1,o1}
        ull w00 = pack2(w.x, w.x), w01 = pack2(w.y, w.y);
        ull w10 = pack2(w.z, w.z), w11 = pack2(w.w, w.w);
        const ull* xa = (const ull*)(sh_s + (2 * c2) * TILE + tb);
        const ull* xb = (const ull*)(sh_s + (2 * c2 + 1) * TILE + tb);
        #pragma unroll
        for (int p = 0; p < 8; ++p) {
            ull x0 = xa[p], x1 = xb[p];
            ffma2(o0[p], w00, x0); ffma2(o0[p], w10, x1);
            ffma2(o1[p], w01, x0); ffma2(o1[p], w11, x1);
        }
    }
    const ull* hr0 = (const ull*)(sh_hcur + ca * TILE + tb);
    const ull* hr1 = (const ull*)(sh_hcur + (ca + 1) * TILE + tb);
    #pragma unroll
    for (int p = 0; p < 8; ++p) {
        *(ull*)(h_out + ca * TT_ + t0 + tb + 2 * p)       = fadd2(o0[p], hr0[p]);
        *(ull*)(h_out + (ca + 1) * TT_ + t0 + tb + 2 * p) = fadd2(o1[p], hr1[p]);
    }
}

// ---------------- head: relu -> lin1 -> relu -> lin2, [B,C,T] -> [T,B,C] ----------------
__global__ __launch_bounds__(NTH, 2)
void final_kernel(const float* __restrict__ l1b,
                  const float* __restrict__ l2b,
                  float* __restrict__ out) {
    extern __shared__ float sm[];
    float* sh_s = sm;            // 32KB
    float* sh_z = sm + 8192;     // 32KB

    const int tid  = threadIdx.x;
    const int tile = blockIdx.x;
    const int b    = tile >> 7;
    const int t0   = (tile & 127) * TILE;
    const float* skp = g_skip + (size_t)b * HB;

    #pragma unroll
    for (int it = 0; it < 8; ++it) {
        int v = tid + it * NTH;
        int c = v >> 4, q = v & 15;
        float4 x = __ldg((const float4*)(skp + c * TT_ + t0 + q * 4));
        x.x = fmaxf(x.x, 0.f); x.y = fmaxf(x.y, 0.f);
        x.z = fmaxf(x.z, 0.f); x.w = fmaxf(x.w, 0.f);
        *(float4*)(sh_s + c * TILE + q * 4) = x;
    }
    __syncthreads();

    const int og = tid >> 2, tg = tid & 3;
    const int tb = tg * 16, o2 = 2 * og;

    // GEMM1
    ull a0[8], a1[8];
    {
        float b0 = l1b[o2], b1 = l1b[o2 + 1];
        #pragma unroll
        for (int p = 0; p < 8; ++p) { a0[p] = pack2(b0, b0); a1[p] = pack2(b1, b1); }
    }
    const float4* w1p = (const float4*)g_l1t + og;
    #pragma unroll 2
    for (int c2 = 0; c2 < 64; ++c2) {
        float4 w = __ldg(w1p + c2 * 64);
        ull w00 = pack2(w.x, w.x), w01 = pack2(w.y, w.y);
        ull w10 = pack2(w.z, w.z), w11 = pack2(w.w, w.w);
        const ull* xa = (const ull*)(sh_s + (2 * c2) * TILE + tb);
        const ull* xb = (const ull*)(sh_s + (2 * c2 + 1) * TILE + tb);
        #pragma unroll
        for (int p = 0; p < 8; ++p) {
            ull x0 = xa[p], x1 = xb[p];
            ffma2(a0[p], w00, x0); ffma2(a0[p], w10, x1);
            ffma2(a1[p], w01, x0); ffma2(a1[p], w11, x1);
        }
    }
    #pragma unroll
    for (int p = 0; p < 8; ++p) {
        float lo, hi;
        unpack2(a0[p], lo, hi);
        sh_z[o2 * TILE + tb + 2 * p]     = fmaxf(lo, 0.f);
        sh_z[o2 * TILE + tb + 2 * p + 1] = fmaxf(hi, 0.f);
        unpack2(a1[p], lo, hi);
        sh_z[(o2 + 1) * TILE + tb + 2 * p]     = fmaxf(lo, 0.f);
        sh_z[(o2 + 1) * TILE + tb + 2 * p + 1] = fmaxf(hi, 0.f);
    }
    __syncthreads();

    // GEMM2
    ull c0[8], c1[8];
    {
        float b0 = l2b[o2], b1 = l2b[o2 + 1];
        #pragma unroll
        for (int p = 0; p < 8; ++p) { c0[p] = pack2(b0, b0); c1[p] = pack2(b1, b1); }
    }
    const float4* w2p = (const float4*)g_l2t + og;
    #pragma unroll 2
    for (int c2 = 0; c2 < 64; ++c2) {
        float4 w = __ldg(w2p + c2 * 64);
        ull w00 = pack2(w.x, w.x), w01 = pack2(w.y, w.y);
        ull w10 = pack2(w.z, w.z), w11 = pack2(w.w, w.w);
        const ull* xa = (const ull*)(sh_z + (2 * c2) * TILE + tb);
        const ull* xb = (const ull*)(sh_z + (2 * c2 + 1) * TILE + tb);
        #pragma unroll
        for (int p = 0; p < 8; ++p) {
            ull x0 = xa[p], x1 = xb[p];
            ffma2(c0[p], w00, x0); ffma2(c0[p], w10, x1);
            ffma2(c1[p], w01, x0); ffma2(c1[p], w11, x1);
        }
    }
    // out layout [T, B, 128]
    #pragma unroll
    for (int p = 0; p < 8; ++p) {
        float lo0, hi0, lo1, hi1;
        unpack2(c0[p], lo0, hi0); unpack2(c1[p], lo1, hi1);
        int t = t0 + tb + 2 * p;
        *(float2*)(out + ((size_t)t * BB + b) * CIN + o2)       = make_float2(lo0, lo1);
        *(float2*)(out + ((size_t)(t + 1) * BB + b) * CIN + o2) = make_float2(hi0, hi1);
    }
}

// ---------------- host launcher ----------------
extern "C" void kernel_launch(void* const* d_in, const int* in_sizes, int n_in,
                              void* d_out, int out_size) {
    const float* x      = (const float*)d_in[0];
    const float* pre_w  = (const float*)d_in[1];
    const float* pre_b  = (const float*)d_in[2];
    const float* conv_w = (const float*)d_in[3];
    const float* conv_b = (const float*)d_in[4];
    const float* post_w = (const float*)d_in[5];
    const float* post_b = (const float*)d_in[6];
    const float* lin1_w = (const float*)d_in[7];
    const float* lin1_b = (const float*)d_in[8];
    const float* lin2_w = (const float*)d_in[9];
    const float* lin2_b = (const float*)d_in[10];
    float* out = (float*)d_out;

    const int SMEM_L = 24576 * (int)sizeof(float);   // 96 KB
    const int SMEM_F = 16384 * (int)sizeof(float);   // 64 KB
    cudaFuncSetAttribute(layer_kernel, cudaFuncAttributeMaxDynamicSharedMemorySize, SMEM_L);
    cudaFuncSetAttribute(final_kernel, cudaFuncAttributeMaxDynamicSharedMemorySize, SMEM_F);

    prep_kernel<<<2048, 256>>>(conv_w, post_w, lin1_w, lin2_w);
    pre_kernel<<<2048, 256>>>(x, pre_w, pre_b);

    int parity = 0;
    for (int i = 0; i < NL; ++i) {
        int d = 1 << (i % 10);
        layer_kernel<<<BB * (TT_ / TILE), NTH, SMEM_L>>>(i, d, parity, conv_b, post_b);
        parity ^= 1;
    }
    final_kernel<<<BB * (TT_ / TILE), NTH, SMEM_F>>>(lin1_b, lin2_b, out);
}